// round 9
// baseline (speedup 1.0000x reference)
#include <cuda_runtime.h>
#include <cuda_fp16.h>
#include <cstdint>

// ============================================================
// Detect head via mma.sync, fp16 operands / fp32 accum.
// R9: 3 CTAs/SM (launch_bounds 256,3) + register-trimmed
// addressing; double-buffered smem, ldmatrix B fragments.
// ============================================================

#define TPB 256
#define SROW 88

#define XS0 0            // 32 k-rows x 256B (swizzled fp16)
#define XS1 8192
#define WS0 16384        // 96 n-rows x 80B
#define WS1 24064
#define SMEM_BYTES 31744 // epilogue S union: 64*88*4 = 22528

__device__ __forceinline__ uint32_t smem_u32(const void* p) {
    uint32_t a;
    asm("{ .reg .u64 t; cvta.to.shared.u64 t, %1; cvt.u32.u64 %0, t; }" : "=r"(a) : "l"(p));
    return a;
}

#define LDMX4T(r, addr) \
    asm volatile("ldmatrix.sync.aligned.m8n8.x4.trans.shared.b16 {%0,%1,%2,%3}, [%4];" \
        : "=r"((r)[0]), "=r"((r)[1]), "=r"((r)[2]), "=r"((r)[3]) : "r"(addr))

#define LDMX4(r, addr) \
    asm volatile("ldmatrix.sync.aligned.m8n8.x4.shared.b16 {%0,%1,%2,%3}, [%4];" \
        : "=r"((r)[0]), "=r"((r)[1]), "=r"((r)[2]), "=r"((r)[3]) : "r"(addr))

#define MMA16816(d, a, b0, b1) \
    asm volatile("mma.sync.aligned.m16n8k16.row.col.f32.f16.f16.f32 " \
        "{%0,%1,%2,%3}, {%4,%5,%6,%7}, {%8,%9}, {%0,%1,%2,%3};" \
        : "+f"((d)[0]), "+f"((d)[1]), "+f"((d)[2]), "+f"((d)[3]) \
        : "r"((a)[0]), "r"((a)[1]), "r"((a)[2]), "r"((a)[3]), "r"(b0), "r"(b1))

#define CP_ASYNC16(dst, src) \
    asm volatile("cp.async.ca.shared.global [%0], [%1], 16;" :: "r"(dst), "l"(src))
#define CP_COMMIT() asm volatile("cp.async.commit_group;" ::: "memory")
#define CP_WAIT0()  asm volatile("cp.async.wait_group 0;" ::: "memory")

// 56 chunks of 32 channels: [96 n][32 k] fp16 each
__device__ __align__(16) __half g_Wh[56 * 96 * 32];

__global__ void prep_W(const float* __restrict__ W0, const float* __restrict__ W1,
                       const float* __restrict__ W2)
{
    int idx = blockIdx.x * blockDim.x + threadIdx.x;
    if (idx >= 56 * 96 * 32) return;
    int ch = idx / 3072, rem = idx - ch * 3072;
    int n = rem >> 5, k = rem & 31;
    const float* W; int C, cb;
    if (ch < 8)       { W = W0; C = 256;  cb = ch * 32; }
    else if (ch < 24) { W = W1; C = 512;  cb = (ch - 8) * 32; }
    else              { W = W2; C = 1024; cb = (ch - 24) * 32; }
    float v = (n < 85) ? W[(size_t)n * C + cb + k] : 0.0f;
    g_Wh[idx] = __float2half(v);
}

__device__ __forceinline__ uint32_t h2u(__half2 h) {
    return *reinterpret_cast<uint32_t*>(&h);
}

template <int C, int NHW, int NX, int LEVEL>
__device__ __forceinline__
void run_level(const float* __restrict__ X, const float* __restrict__ bias,
               float* __restrict__ out, int lvlOff, int chBase, int b, int m0,
               char* sm, uint32_t sb)
{
    const int tid = threadIdx.x;
    const int lane = tid & 31, wid = tid >> 5;
    const int wm = wid >> 1, wn = wid & 1;
    constexpr int NCH = C / 32;
    const bool fullTile = (m0 + 128 <= NHW);
    const float* Xb = X + (size_t)b * C * NHW;

    float acc[2][6][4];
#pragma unroll
    for (int mf = 0; mf < 2; mf++)
#pragma unroll
        for (int f = 0; f < 6; f++)
#pragma unroll
            for (int e = 0; e < 4; e++) acc[mf][f][e] = 0.0f;

    // ---- trimmed hoisted addresses ----
    // X staging: k rows step by +8 per it; (k&7) is it-invariant.
    const int k0 = tid >> 5, m4 = tid & 31;
    const uint32_t offX0 = (uint32_t)(k0 * 256 + ((m4 * 8) ^ ((k0 & 7) << 4)));
    const float* pxBase = Xb + (size_t)k0 * NHW + m0 + m4 * 4;   // advanced by 32*NHW per chunk

    // A ldmatrix: ks-invariant base offsets
    uint32_t aoffA[2];
    {
        const int mat = lane >> 3, r = lane & 7;
#pragma unroll
        for (int mf = 0; mf < 2; mf++) {
            int kb = ((mat >> 1) << 3) + r;
            int mb = (wm * 32 + mf * 16 + ((mat & 1) << 3)) * 2;
            aoffA[mf] = (uint32_t)(kb * 256 + (mb ^ (r << 4)));
        }
    }
    // B ldmatrix.x4: 3 per ks, each covers 2 f-tiles
    uint32_t relB[3];
    {
        const int grp = lane >> 3, rsel = lane & 7;
#pragma unroll
        for (int j = 0; j < 3; j++)
            relB[j] = (uint32_t)((wn * 48 + (j * 2 + (grp >> 1)) * 8 + rsel) * 80
                                 + (grp & 1) * 16);
    }
    // W cp.async dst offsets
    const uint32_t wrel0 = (uint32_t)((tid >> 2) * 80 + (tid & 3) * 16);
    const uint32_t wrel1 = (uint32_t)(((tid + 256) >> 2) * 80 + (tid & 3) * 16);

    auto loadX = [&](int chk, float4 (&v)[4]) {
        if (fullTile) {
            const float* p = pxBase + (size_t)chk * 32 * NHW;
#pragma unroll
            for (int it = 0; it < 4; it++)
                v[it] = *reinterpret_cast<const float4*>(p + (size_t)(8 * it) * NHW);
        } else {
            int lim = NHW - 1 - m0;
#pragma unroll
            for (int it = 0; it < 4; it++) {
                const float* src = Xb + (size_t)(chk * 32 + k0 + 8 * it) * NHW + m0;
                v[it].x = src[min(m4 * 4 + 0, lim)];
                v[it].y = src[min(m4 * 4 + 1, lim)];
                v[it].z = src[min(m4 * 4 + 2, lim)];
                v[it].w = src[min(m4 * 4 + 3, lim)];
            }
        }
    };

    auto convertX = [&](const float4 (&v)[4], uint32_t xsOff) {
#pragma unroll
        for (int it = 0; it < 4; it++) {
            __half2 h0 = __floats2half2_rn(v[it].x, v[it].y);
            __half2 h1 = __floats2half2_rn(v[it].z, v[it].w);
            *reinterpret_cast<uint2*>(sm + xsOff + offX0 + it * 2048) =
                make_uint2(h2u(h0), h2u(h1));
        }
    };

    auto stageW = [&](int chk, uint32_t wsOff) {
        const uint4* wsrc = reinterpret_cast<const uint4*>(
            &g_Wh[(size_t)(chBase + chk) * 3072]);
        CP_ASYNC16(sb + wsOff + wrel0, wsrc + tid);
        if (tid < 128) CP_ASYNC16(sb + wsOff + wrel1, wsrc + tid + 256);
        CP_COMMIT();
    };

    // ---- prologue: stage chunk 0, prefetch chunk 1 ----
    float4 v[4];
    loadX(0, v);
    stageW(0, WS0);
    convertX(v, XS0);
    loadX(1, v);
    CP_WAIT0();
    __syncthreads();

    for (int chk = 0; chk < NCH; chk++) {
        const uint32_t xsCur = (chk & 1) ? XS1 : XS0;
        const uint32_t wsCur = (chk & 1) ? WS1 : WS0;

        // ---- stage chunk+1 into the other buffer ----
        if (chk + 1 < NCH) {
            stageW(chk + 1, (chk & 1) ? WS0 : WS1);
            convertX(v, (chk & 1) ? XS0 : XS1);
            if (chk + 2 < NCH) loadX(chk + 2, v);
        }

        // ---- MMA on current buffers ----
        const uint32_t xbase = sb + xsCur;
        const uint32_t wbase = sb + wsCur;
#pragma unroll
        for (int ks = 0; ks < 2; ks++) {
            uint32_t af[2][4];
            LDMX4T(af[0], xbase + aoffA[0] + ks * 4096);
            LDMX4T(af[1], xbase + aoffA[1] + ks * 4096);
#pragma unroll
            for (int j = 0; j < 3; j++) {
                uint32_t br[4];
                LDMX4(br, wbase + relB[j] + ks * 32);
                MMA16816(acc[0][2 * j + 0], af[0], br[0], br[1]);
                MMA16816(acc[1][2 * j + 0], af[1], br[0], br[1]);
                MMA16816(acc[0][2 * j + 1], af[0], br[2], br[3]);
                MMA16816(acc[1][2 * j + 1], af[1], br[2], br[3]);
            }
        }

        CP_WAIT0();
        __syncthreads();
    }

    // ---- bias + sigmoid ----
    const int g = lane >> 2, c0 = lane & 3;
#pragma unroll
    for (int f = 0; f < 6; f++) {
        int nb = wn * 48 + f * 8 + c0 * 2;
        float bv0 = (nb < 85) ? __ldg(&bias[nb]) : 0.0f;
        float bv1 = (nb + 1 < 85) ? __ldg(&bias[nb + 1]) : 0.0f;
#pragma unroll
        for (int mf = 0; mf < 2; mf++)
#pragma unroll
            for (int h = 0; h < 2; h++) {
                float p0 = acc[mf][f][h * 2 + 0] + bv0;
                float p1 = acc[mf][f][h * 2 + 1] + bv1;
                acc[mf][f][h * 2 + 0] = __fdividef(1.0f, 1.0f + __expf(-p0));
                acc[mf][f][h * 2 + 1] = __fdividef(1.0f, 1.0f + __expf(-p1));
            }
    }

    // ---- box decode (channels 0..3 live in wn==0, f==0, c0<2) ----
    if (wn == 0) {
        const float power = (float)(1 << LEVEL);
        const float strd  = (float)(8 << LEVEL);
#pragma unroll
        for (int mf = 0; mf < 2; mf++)
#pragma unroll
            for (int h = 0; h < 2; h++) {
                float s0 = acc[mf][0][h * 2 + 0];
                float s1 = acc[mf][0][h * 2 + 1];
                float q0 = 4.0f * s0 * s0 * power;
                float q1 = 4.0f * s1 * s1 * power;
                float p0 = __shfl_xor_sync(0xffffffffu, q0, 1);
                float p1 = __shfl_xor_sync(0xffffffffu, q1, 1);
                float dx1 = (c0 == 0) ? q0 : p0;
                float dy1 = (c0 == 0) ? q1 : p1;
                float dx2 = (c0 == 0) ? p0 : q0;
                float dy2 = (c0 == 0) ? p1 : q1;
                int pos = m0 + wm * 32 + mf * 16 + h * 8 + g;
                int iy = pos / NX, ix = pos - iy * NX;
                float x1 = ((float)ix + 1.0f - dx1) * strd;
                float y1 = ((float)iy + 1.0f - dy1) * strd;
                float x2 = ((float)ix + dx2) * strd;
                float y2 = ((float)iy + dy2) * strd;
                if (c0 == 0) {
                    acc[mf][0][h * 2 + 0] = 0.5f * (x1 + x2);
                    acc[mf][0][h * 2 + 1] = 0.5f * (y1 + y2);
                } else if (c0 == 1) {
                    acc[mf][0][h * 2 + 0] = x2 - x1;
                    acc[mf][0][h * 2 + 1] = y2 - y1;
                }
            }
    }

    // ---- staged coalesced store: 2 waves of 64 positions ----
    float* S = reinterpret_cast<float*>(sm);
#pragma unroll
    for (int w = 0; w < 2; w++) {
        __syncthreads();
        if ((wm >> 1) == w) {
            int mbase = (wm & 1) * 32;
#pragma unroll
            for (int mf = 0; mf < 2; mf++)
#pragma unroll
                for (int h = 0; h < 2; h++) {
                    int mrow = mbase + mf * 16 + h * 8 + g;
#pragma unroll
                    for (int f = 0; f < 6; f++) {
                        int n = wn * 48 + f * 8 + c0 * 2;
                        if (n + 1 < 85)
                            *reinterpret_cast<float2*>(&S[mrow * SROW + n]) =
                                make_float2(acc[mf][f][h * 2], acc[mf][f][h * 2 + 1]);
                        else if (n < 85)
                            S[mrow * SROW + n] = acc[mf][f][h * 2];
                    }
                }
        }
        __syncthreads();
        int valid = NHW - (m0 + w * 64);
        valid = valid < 0 ? 0 : (valid > 64 ? 64 : valid);
        int total = valid * 85;
        float* ob = out + ((size_t)b * 8400 + lvlOff + m0 + w * 64) * 85;
        for (int i = tid; i < total; i += TPB) {
            int p = i / 85, o = i - p * 85;
            ob[i] = S[p * SROW + o];
        }
    }
}

// grid order: L2 (longest, 32 chunks) first, then L1, then L0
__global__ __launch_bounds__(TPB, 3)
void detect_tc(const float* __restrict__ x0, const float* __restrict__ x1,
               const float* __restrict__ x2,
               const float* __restrict__ b0, const float* __restrict__ b1,
               const float* __restrict__ b2, float* __restrict__ out)
{
    __shared__ __align__(1024) char sm[SMEM_BYTES];
    uint32_t sb = smem_u32(sm);
    int bid = blockIdx.x;
    if (bid < 64) {                      // L2: 4 tiles x 16 batch
        int b = bid >> 2, t = bid & 3;
        run_level<1024, 400, 20, 2>(x2, b2, out, 8000, 24, b, t * 128, sm, sb);
    } else if (bid < 272) {              // L1: 13 tiles x 16 batch
        int q = bid - 64;
        int b = q / 13, t = q - b * 13;
        run_level<512, 1600, 40, 1>(x1, b1, out, 6400, 8, b, t * 128, sm, sb);
    } else {                             // L0: 50 tiles x 16 batch
        int q = bid - 272;
        int b = q / 50, t = q - b * 50;
        run_level<256, 6400, 80, 0>(x0, b0, out, 0, 0, b, t * 128, sm, sb);
    }
}

extern "C" void kernel_launch(void* const* d_in, const int* in_sizes, int n_in,
                              void* d_out, int out_size)
{
    const float* x0 = (const float*)d_in[0];
    const float* x1 = (const float*)d_in[1];
    const float* x2 = (const float*)d_in[2];
    const float* W0 = (const float*)d_in[3];
    const float* b0 = (const float*)d_in[4];
    const float* W1 = (const float*)d_in[5];
    const float* b1 = (const float*)d_in[6];
    const float* W2 = (const float*)d_in[7];
    const float* b2 = (const float*)d_in[8];
    float* out = (float*)d_out;

    prep_W<<<(56 * 96 * 32 + 255) / 256, 256>>>(W0, W1, W2);
    detect_tc<<<64 + 208 + 800, TPB>>>(x0, x1, x2, b0, b1, b2, out);
}

// round 11
// speedup vs baseline: 1.2500x; 1.2500x over previous
#include <cuda_runtime.h>
#include <cuda_fp16.h>
#include <cstdint>

// ============================================================
// Detect head via mma.sync, fp16 operands / fp32 accum.
// R11 (= R10 resubmit): K-chunk=64 (half the barriers),
// double-buffered dynamic smem, two-wave X staging with halfB
// hidden under the MMA phase. 128 regs / 2 CTAs per SM.
// ============================================================

#define TPB 256
#define SROW 88

// dynamic smem layout
#define XS0 0            // 64 k-rows x 256B (swizzled fp16) = 16384
#define XS1 16384
#define WS0 32768        // 96 n-rows x 144B = 13824
#define WS1 46592
#define SMEM_BYTES 60416

__device__ __forceinline__ uint32_t smem_u32(const void* p) {
    uint32_t a;
    asm("{ .reg .u64 t; cvta.to.shared.u64 t, %1; cvt.u32.u64 %0, t; }" : "=r"(a) : "l"(p));
    return a;
}

#define LDMX4T(r, addr) \
    asm volatile("ldmatrix.sync.aligned.m8n8.x4.trans.shared.b16 {%0,%1,%2,%3}, [%4];" \
        : "=r"((r)[0]), "=r"((r)[1]), "=r"((r)[2]), "=r"((r)[3]) : "r"(addr))

#define LDMX4(r, addr) \
    asm volatile("ldmatrix.sync.aligned.m8n8.x4.shared.b16 {%0,%1,%2,%3}, [%4];" \
        : "=r"((r)[0]), "=r"((r)[1]), "=r"((r)[2]), "=r"((r)[3]) : "r"(addr))

#define MMA16816(d, a, b0, b1) \
    asm volatile("mma.sync.aligned.m16n8k16.row.col.f32.f16.f16.f32 " \
        "{%0,%1,%2,%3}, {%4,%5,%6,%7}, {%8,%9}, {%0,%1,%2,%3};" \
        : "+f"((d)[0]), "+f"((d)[1]), "+f"((d)[2]), "+f"((d)[3]) \
        : "r"((a)[0]), "r"((a)[1]), "r"((a)[2]), "r"((a)[3]), "r"(b0), "r"(b1))

#define CP_ASYNC16(dst, src) \
    asm volatile("cp.async.ca.shared.global [%0], [%1], 16;" :: "r"(dst), "l"(src))
#define CP_COMMIT() asm volatile("cp.async.commit_group;" ::: "memory")
#define CP_WAIT0()  asm volatile("cp.async.wait_group 0;" ::: "memory")

// 28 chunks of 64 channels: [96 n][64 k] fp16 each (12 KB)
__device__ __align__(16) __half g_Wh[28 * 96 * 64];

__global__ void prep_W(const float* __restrict__ W0, const float* __restrict__ W1,
                       const float* __restrict__ W2)
{
    int idx = blockIdx.x * blockDim.x + threadIdx.x;
    if (idx >= 28 * 96 * 64) return;
    int ch = idx / 6144, rem = idx - ch * 6144;
    int n = rem >> 6, k = rem & 63;
    const float* W; int C, cb;
    if (ch < 4)       { W = W0; C = 256;  cb = ch * 64; }
    else if (ch < 12) { W = W1; C = 512;  cb = (ch - 4) * 64; }
    else              { W = W2; C = 1024; cb = (ch - 12) * 64; }
    float v = (n < 85) ? W[(size_t)n * C + cb + k] : 0.0f;
    g_Wh[idx] = __float2half(v);
}

__device__ __forceinline__ uint32_t h2u(__half2 h) {
    return *reinterpret_cast<uint32_t*>(&h);
}

template <int C, int NHW, int NX, int LEVEL>
__device__ __forceinline__
void run_level(const float* __restrict__ X, const float* __restrict__ bias,
               float* __restrict__ out, int lvlOff, int chBase, int b, int m0,
               char* sm, uint32_t sb)
{
    const int tid = threadIdx.x;
    const int lane = tid & 31, wid = tid >> 5;
    const int wm = wid >> 1, wn = wid & 1;
    constexpr int NCH = C / 64;
    const bool fullTile = (m0 + 128 <= NHW);
    const float* Xb = X + (size_t)b * C * NHW;

    float acc[2][6][4];
#pragma unroll
    for (int mf = 0; mf < 2; mf++)
#pragma unroll
        for (int f = 0; f < 6; f++)
#pragma unroll
            for (int e = 0; e < 4; e++) acc[mf][f][e] = 0.0f;

    // ---- hoisted addresses ----
    const int k0 = tid >> 5, m4 = tid & 31;
    const uint32_t offX0 = (uint32_t)(k0 * 256 + ((m4 * 8) ^ ((k0 & 7) << 4)));

    uint32_t aoffA[2];
    {
        const int mat = lane >> 3, r = lane & 7;
#pragma unroll
        for (int mf = 0; mf < 2; mf++) {
            int kb = ((mat >> 1) << 3) + r;
            int mb = (wm * 32 + mf * 16 + ((mat & 1) << 3)) * 2;
            aoffA[mf] = (uint32_t)(kb * 256 + (mb ^ (r << 4)));
        }
    }
    uint32_t relB[3];
    {
        const int grp = lane >> 3, rsel = lane & 7;
#pragma unroll
        for (int j = 0; j < 3; j++)
            relB[j] = (uint32_t)((wn * 48 + (j * 2 + (grp >> 1)) * 8 + rsel) * 144
                                 + (grp & 1) * 16);
    }

    // load half (32 k-rows) of a chunk into 4 float4 regs
    auto loadX = [&](int chk, int half, float4 (&v)[4]) {
        const int rbase = chk * 64 + half * 32 + k0;
        if (fullTile) {
            const float* p = Xb + (size_t)rbase * NHW + m0 + m4 * 4;
#pragma unroll
            for (int it = 0; it < 4; it++)
                v[it] = *reinterpret_cast<const float4*>(p + (size_t)(8 * it) * NHW);
        } else {
            int lim = NHW - 1 - m0;
#pragma unroll
            for (int it = 0; it < 4; it++) {
                const float* src = Xb + (size_t)(rbase + 8 * it) * NHW + m0;
                v[it].x = src[min(m4 * 4 + 0, lim)];
                v[it].y = src[min(m4 * 4 + 1, lim)];
                v[it].z = src[min(m4 * 4 + 2, lim)];
                v[it].w = src[min(m4 * 4 + 3, lim)];
            }
        }
    };

    auto convertX = [&](const float4 (&v)[4], uint32_t xsOff, int half) {
        uint32_t base = xsOff + offX0 + (uint32_t)half * 8192;
#pragma unroll
        for (int it = 0; it < 4; it++) {
            __half2 h0 = __floats2half2_rn(v[it].x, v[it].y);
            __half2 h1 = __floats2half2_rn(v[it].z, v[it].w);
            *reinterpret_cast<uint2*>(sm + base + it * 2048) = make_uint2(h2u(h0), h2u(h1));
        }
    };

    // W: 96 rows x 128B = 768 x 16B units; thread does units tid, +256, +512
    auto stageW = [&](int chk, uint32_t wsOff) {
        const uint4* wsrc = reinterpret_cast<const uint4*>(
            &g_Wh[(size_t)(chBase + chk) * 6144]);
#pragma unroll
        for (int it = 0; it < 3; it++) {
            uint32_t u = tid + it * TPB;
            CP_ASYNC16(sb + wsOff + (u >> 3) * 144 + (u & 7) * 16, wsrc + u);
        }
        CP_COMMIT();
    };

    // ---- prologue ----
    float4 v[4];
    loadX(0, 0, v);
    stageW(0, WS0);
    convertX(v, XS0, 0);
    loadX(0, 1, v);
    convertX(v, XS0, 1);          // one exposed load, prologue only
    loadX(1 < NCH ? 1 : 0, 0, v);
    CP_WAIT0();
    __syncthreads();

    for (int chk = 0; chk < NCH; chk++) {
        const uint32_t xsCur = (chk & 1) ? XS1 : XS0;
        const uint32_t wsCur = (chk & 1) ? WS1 : WS0;
        const uint32_t xsNxt = (chk & 1) ? XS0 : XS1;
        const uint32_t wsNxt = (chk & 1) ? WS0 : WS1;

        if (chk + 1 < NCH) {
            stageW(chk + 1, wsNxt);
            convertX(v, xsNxt, 0);          // halfA of next
            loadX(chk + 1, 1, v);           // halfB load flies under MMA
        }

        // ---- MMA on current buffers: 4 k16 steps ----
        const uint32_t xbase = sb + xsCur;
        const uint32_t wbase = sb + wsCur;
#pragma unroll
        for (int ks = 0; ks < 4; ks++) {
            uint32_t af[2][4];
            LDMX4T(af[0], xbase + aoffA[0] + ks * 4096);
            LDMX4T(af[1], xbase + aoffA[1] + ks * 4096);
#pragma unroll
            for (int j = 0; j < 3; j++) {
                uint32_t br[4];
                LDMX4(br, wbase + relB[j] + ks * 32);
                MMA16816(acc[0][2 * j + 0], af[0], br[0], br[1]);
                MMA16816(acc[1][2 * j + 0], af[1], br[0], br[1]);
                MMA16816(acc[0][2 * j + 1], af[0], br[2], br[3]);
                MMA16816(acc[1][2 * j + 1], af[1], br[2], br[3]);
            }
        }

        if (chk + 1 < NCH) {
            convertX(v, xsNxt, 1);          // halfB of next (other buffer, no hazard)
            if (chk + 2 < NCH) loadX(chk + 2, 0, v);
        }
        CP_WAIT0();
        __syncthreads();
    }

    // ---- bias + sigmoid ----
    const int g = lane >> 2, c0 = lane & 3;
#pragma unroll
    for (int f = 0; f < 6; f++) {
        int nb = wn * 48 + f * 8 + c0 * 2;
        float bv0 = (nb < 85) ? __ldg(&bias[nb]) : 0.0f;
        float bv1 = (nb + 1 < 85) ? __ldg(&bias[nb + 1]) : 0.0f;
#pragma unroll
        for (int mf = 0; mf < 2; mf++)
#pragma unroll
            for (int h = 0; h < 2; h++) {
                float p0 = acc[mf][f][h * 2 + 0] + bv0;
                float p1 = acc[mf][f][h * 2 + 1] + bv1;
                acc[mf][f][h * 2 + 0] = __fdividef(1.0f, 1.0f + __expf(-p0));
                acc[mf][f][h * 2 + 1] = __fdividef(1.0f, 1.0f + __expf(-p1));
            }
    }

    // ---- box decode (channels 0..3 live in wn==0, f==0, c0<2) ----
    if (wn == 0) {
        const float power = (float)(1 << LEVEL);
        const float strd  = (float)(8 << LEVEL);
#pragma unroll
        for (int mf = 0; mf < 2; mf++)
#pragma unroll
            for (int h = 0; h < 2; h++) {
                float s0 = acc[mf][0][h * 2 + 0];
                float s1 = acc[mf][0][h * 2 + 1];
                float q0 = 4.0f * s0 * s0 * power;
                float q1 = 4.0f * s1 * s1 * power;
                float p0 = __shfl_xor_sync(0xffffffffu, q0, 1);
                float p1 = __shfl_xor_sync(0xffffffffu, q1, 1);
                float dx1 = (c0 == 0) ? q0 : p0;
                float dy1 = (c0 == 0) ? q1 : p1;
                float dx2 = (c0 == 0) ? p0 : q0;
                float dy2 = (c0 == 0) ? p1 : q1;
                int pos = m0 + wm * 32 + mf * 16 + h * 8 + g;
                int iy = pos / NX, ix = pos - iy * NX;
                float x1 = ((float)ix + 1.0f - dx1) * strd;
                float y1 = ((float)iy + 1.0f - dy1) * strd;
                float x2 = ((float)ix + dx2) * strd;
                float y2 = ((float)iy + dy2) * strd;
                if (c0 == 0) {
                    acc[mf][0][h * 2 + 0] = 0.5f * (x1 + x2);
                    acc[mf][0][h * 2 + 1] = 0.5f * (y1 + y2);
                } else if (c0 == 1) {
                    acc[mf][0][h * 2 + 0] = x2 - x1;
                    acc[mf][0][h * 2 + 1] = y2 - y1;
                }
            }
    }

    // ---- staged coalesced store: 2 waves of 64 positions ----
    float* S = reinterpret_cast<float*>(sm);
#pragma unroll
    for (int w = 0; w < 2; w++) {
        __syncthreads();
        if ((wm >> 1) == w) {
            int mbase = (wm & 1) * 32;
#pragma unroll
            for (int mf = 0; mf < 2; mf++)
#pragma unroll
                for (int h = 0; h < 2; h++) {
                    int mrow = mbase + mf * 16 + h * 8 + g;
#pragma unroll
                    for (int f = 0; f < 6; f++) {
                        int n = wn * 48 + f * 8 + c0 * 2;
                        if (n + 1 < 85)
                            *reinterpret_cast<float2*>(&S[mrow * SROW + n]) =
                                make_float2(acc[mf][f][h * 2], acc[mf][f][h * 2 + 1]);
                        else if (n < 85)
                            S[mrow * SROW + n] = acc[mf][f][h * 2];
                    }
                }
        }
        __syncthreads();
        int valid = NHW - (m0 + w * 64);
        valid = valid < 0 ? 0 : (valid > 64 ? 64 : valid);
        int total = valid * 85;
        float* ob = out + ((size_t)b * 8400 + lvlOff + m0 + w * 64) * 85;
        for (int i = tid; i < total; i += TPB) {
            int p = i / 85, o = i - p * 85;
            ob[i] = S[p * SROW + o];
        }
    }
}

// grid order: L2 (longest, 16 chunks) first, then L1, then L0
__global__ __launch_bounds__(TPB, 2)
void detect_tc(const float* __restrict__ x0, const float* __restrict__ x1,
               const float* __restrict__ x2,
               const float* __restrict__ b0, const float* __restrict__ b1,
               const float* __restrict__ b2, float* __restrict__ out)
{
    extern __shared__ __align__(1024) char sm[];
    uint32_t sb = smem_u32(sm);
    int bid = blockIdx.x;
    if (bid < 64) {                      // L2: 4 tiles x 16 batch
        int b = bid >> 2, t = bid & 3;
        run_level<1024, 400, 20, 2>(x2, b2, out, 8000, 12, b, t * 128, sm, sb);
    } else if (bid < 272) {              // L1: 13 tiles x 16 batch
        int q = bid - 64;
        int b = q / 13, t = q - b * 13;
        run_level<512, 1600, 40, 1>(x1, b1, out, 6400, 4, b, t * 128, sm, sb);
    } else {                             // L0: 50 tiles x 16 batch
        int q = bid - 272;
        int b = q / 50, t = q - b * 50;
        run_level<256, 6400, 80, 0>(x0, b0, out, 0, 0, b, t * 128, sm, sb);
    }
}

extern "C" void kernel_launch(void* const* d_in, const int* in_sizes, int n_in,
                              void* d_out, int out_size)
{
    const float* x0 = (const float*)d_in[0];
    const float* x1 = (const float*)d_in[1];
    const float* x2 = (const float*)d_in[2];
    const float* W0 = (const float*)d_in[3];
    const float* b0 = (const float*)d_in[4];
    const float* W1 = (const float*)d_in[5];
    const float* b1 = (const float*)d_in[6];
    const float* W2 = (const float*)d_in[7];
    const float* b2 = (const float*)d_in[8];
    float* out = (float*)d_out;

    cudaFuncSetAttribute(detect_tc, cudaFuncAttributeMaxDynamicSharedMemorySize,
                         SMEM_BYTES);
    prep_W<<<(28 * 96 * 64 + 255) / 256, 256>>>(W0, W1, W2);
    detect_tc<<<64 + 208 + 800, TPB, SMEM_BYTES>>>(x0, x1, x2, b0, b1, b2, out);
}